// round 8
// baseline (speedup 1.0000x reference)
#include <cuda_runtime.h>

#define BATCH 2048
#define NPTS  4095
#define TPB   512
#define EPT   8            // TPB*EPT = 4096
#define NWARP (TPB/32)     // 16
#define PADN  4096

__device__ float g_partial[BATCH];
__device__ int   g_count = 0;

// dynamic smem: ssx[4096] ssy[4096] ssz[4096] = 48 KB
#define SMEM_BYTES (3 * PADN * 4)

extern __shared__ __align__(16) float sstage[];

__global__ void __launch_bounds__(TPB, 4)
mpd_fused_kernel(const float* __restrict__ o3,
                 const float* __restrict__ s3,
                 const float* __restrict__ o2,
                 const float* __restrict__ s2,
                 const float* __restrict__ df,
                 float* __restrict__ out)
{
    float* ssx = sstage;
    float* ssy = sstage + PADN;
    float* ssz = sstage + 2 * PADN;
    __shared__ float wtot[3][NWARP];
    __shared__ float red[NWARP];
    __shared__ int   is_last;

    const int b = blockIdx.x;
    const int t = threadIdx.x;
    const unsigned lane = t & 31u;
    const unsigned warp = t >> 5;

    const float* __restrict__ s3b = s3 + (size_t)b * (3 * NPTS);
    const float* __restrict__ s2b = s2 + (size_t)b * (3 * NPTS);
    const float* __restrict__ dfb = df + (size_t)b * (2 * NPTS);

    // ---- Phase A: one long coalesced load+trig burst, staged to smem ----
    #pragma unroll
    for (int k = 0; k < EPT; k++) {
        const int i = t + k * TPB;            // lane stride 4B, coalesced
        float vx = 0.f, vy = 0.f, vz = 0.f;
        if (i < NPTS) {                        // only i==4095 fails
            float r3  = s3b[i];
            float th3 = s3b[i + NPTS];
            float ph3 = s3b[i + 2 * NPTS];
            float r2  = s2b[i];
            float th2 = s2b[i + NPTS];
            float ph2 = s2b[i + 2 * NPTS];
            float dt  = dfb[i];
            float dp  = dfb[i + NPTS];

            float st, ct, sp, cp;
            __sincosf(th3 + dt, &st, &ct);
            __sincosf(ph3 + dp, &sp, &cp);
            float rst = r3 * st;
            vx = rst * cp; vy = rst * sp; vz = r3 * ct;
            __sincosf(th2, &st, &ct);
            __sincosf(ph2, &sp, &cp);
            rst = r2 * st;
            vx -= rst * cp; vy -= rst * sp; vz -= r2 * ct;
        }
        ssx[i] = vx; ssy[i] = vy; ssz[i] = vz;   // stride-1, conflict-free
    }
    __syncthreads();                              // barrier #1

    // origin deltas loaded AFTER the load burst (short live range)
    const float dx = o3[b * 3 + 0] - o2[b * 3 + 0];
    const float dy = o3[b * 3 + 1] - o2[b * 3 + 1];
    const float dz = o3[b * 3 + 2] - o2[b * 3 + 2];

    // ---- Phase B1: sum-only sweep (blocked LDS.128) -> thread totals ----
    const int base = t * EPT;                     // 32B aligned
    float tx, ty, tz;
    {
        float4 A = *reinterpret_cast<const float4*>(ssx + base);
        float4 B = *reinterpret_cast<const float4*>(ssx + base + 4);
        tx = (A.x + A.y) + (A.z + A.w) + (B.x + B.y) + (B.z + B.w);
        A = *reinterpret_cast<const float4*>(ssy + base);
        B = *reinterpret_cast<const float4*>(ssy + base + 4);
        ty = (A.x + A.y) + (A.z + A.w) + (B.x + B.y) + (B.z + B.w);
        A = *reinterpret_cast<const float4*>(ssz + base);
        B = *reinterpret_cast<const float4*>(ssz + base + 4);
        tz = (A.x + A.y) + (A.z + A.w) + (B.x + B.y) + (B.z + B.w);
    }

    // warp inclusive scan of thread totals
    float ix = tx, iy = ty, iz = tz;
    #pragma unroll
    for (int o = 1; o < 32; o <<= 1) {
        float ax = __shfl_up_sync(0xFFFFFFFFu, ix, o);
        float ay = __shfl_up_sync(0xFFFFFFFFu, iy, o);
        float az = __shfl_up_sync(0xFFFFFFFFu, iz, o);
        if (lane >= (unsigned)o) { ix += ax; iy += ay; iz += az; }
    }
    if (lane == 31) { wtot[0][warp] = ix; wtot[1][warp] = iy; wtot[2][warp] = iz; }
    __syncthreads();                              // barrier #2

    // ---- all warps redundantly scan the 16 warp totals (no more barriers) ----
    float px = (lane < NWARP) ? wtot[0][lane] : 0.f;
    float py = (lane < NWARP) ? wtot[1][lane] : 0.f;
    float pz = (lane < NWARP) ? wtot[2][lane] : 0.f;
    #pragma unroll
    for (int o = 1; o < NWARP; o <<= 1) {
        float ax = __shfl_up_sync(0xFFFFFFFFu, px, o);
        float ay = __shfl_up_sync(0xFFFFFFFFu, py, o);
        float az = __shfl_up_sync(0xFFFFFFFFu, pz, o);
        if (lane >= (unsigned)o) { px += ax; py += ay; pz += az; }
    }
    const unsigned src = (warp == 0) ? 0u : (warp - 1u);
    float wpx = __shfl_sync(0xFFFFFFFFu, px, src);
    float wpy = __shfl_sync(0xFFFFFFFFu, py, src);
    float wpz = __shfl_sync(0xFFFFFFFFu, pz, src);

    // exclusive offset for this thread's first element
    float offx = dx + (ix - tx) + ((warp == 0) ? 0.f : wpx);
    float offy = dy + (iy - ty) + ((warp == 0) ? 0.f : wpy);
    float offz = dz + (iz - tz) + ((warp == 0) ? 0.f : wpz);

    // ---- Phase B2: re-read smem, running local prefix + abs accumulate ----
    float acc = 0.f;
    if (t == 0) acc = fabsf(dx) + fabsf(dy) + fabsf(dz);   // j=0 (origin)
    #pragma unroll
    for (int h = 0; h < 2; h++) {
        float4 X = *reinterpret_cast<const float4*>(ssx + base + 4 * h);
        float4 Y = *reinterpret_cast<const float4*>(ssy + base + 4 * h);
        float4 Z = *reinterpret_cast<const float4*>(ssz + base + 4 * h);
        float xs[4] = {X.x, X.y, X.z, X.w};
        float ys[4] = {Y.x, Y.y, Y.z, Y.w};
        float zs[4] = {Z.x, Z.y, Z.z, Z.w};
        #pragma unroll
        for (int k = 0; k < 4; k++) {
            offx += xs[k]; offy += ys[k]; offz += zs[k];
            if (base + 4 * h + k < NPTS)
                acc += fabsf(offx) + fabsf(offy) + fabsf(offz);
        }
    }

    // ---- block reduce ----
    #pragma unroll
    for (int o = 16; o > 0; o >>= 1)
        acc += __shfl_down_sync(0xFFFFFFFFu, acc, o);
    if (lane == 0) red[warp] = acc;
    __syncthreads();
    if (warp == 0) {
        float a = (lane < NWARP) ? red[lane] : 0.f;
        #pragma unroll
        for (int o = 16; o > 0; o >>= 1)
            a += __shfl_down_sync(0xFFFFFFFFu, a, o);
        if (lane == 0) g_partial[b] = a * (1.0f / (NPTS + 1));
    }

    // ---- fused deterministic final reduction in the last block ----
    if (t == 0) {
        __threadfence();
        int ticket = atomicAdd(&g_count, 1);
        is_last = (ticket == (int)gridDim.x - 1) ? 1 : 0;
    }
    __syncthreads();
    if (is_last) {
        float a = __ldcg(&g_partial[t])
                + __ldcg(&g_partial[t + TPB])
                + __ldcg(&g_partial[t + 2 * TPB])
                + __ldcg(&g_partial[t + 3 * TPB]);
        #pragma unroll
        for (int o = 16; o > 0; o >>= 1)
            a += __shfl_down_sync(0xFFFFFFFFu, a, o);
        if (lane == 0) red[warp] = a;
        __syncthreads();
        if (warp == 0) {
            float v = (lane < NWARP) ? red[lane] : 0.f;
            #pragma unroll
            for (int o = 16; o > 0; o >>= 1)
                v += __shfl_down_sync(0xFFFFFFFFu, v, o);
            if (lane == 0) {
                out[0] = v;
                atomicExch(&g_count, 0);   // reset for next graph replay
            }
        }
    }
}

extern "C" void kernel_launch(void* const* d_in, const int* in_sizes, int n_in,
                              void* d_out, int out_size)
{
    const float* o3 = (const float*)d_in[0];  // origin_3D        (B,3,1)
    const float* s3 = (const float*)d_in[1];  // spherical_3D     (B,3,N)
    const float* o2 = (const float*)d_in[2];  // origin_2D        (B,3,1)
    const float* s2 = (const float*)d_in[3];  // spherical_2D     (B,3,N)
    const float* df = (const float*)d_in[4];  // deformation_field(B,2,N)
    float* out = (float*)d_out;

    cudaFuncSetAttribute(mpd_fused_kernel,
                         cudaFuncAttributeMaxDynamicSharedMemorySize, SMEM_BYTES);
    mpd_fused_kernel<<<BATCH, TPB, SMEM_BYTES>>>(o3, s3, o2, s2, df, out);
}

// round 9
// speedup vs baseline: 1.3768x; 1.3768x over previous
#include <cuda_runtime.h>

#define BATCH 2048
#define NPTS  4095
#define TPB   512
#define HALF  2048
#define LEPT  4
#define NWARP (TPB/32)     // 16

__device__ float g_partial[BATCH];
__device__ int   g_count = 0;

// dynamic smem: two staging buffers of 3*2048 floats = 2 * 24 KB = 48 KB
#define SMEM_BYTES (2 * 3 * HALF * 4)

extern __shared__ __align__(16) float sstage[];

__global__ void __launch_bounds__(TPB, 3)
mpd_fused_kernel(const float* __restrict__ o3,
                 const float* __restrict__ s3,
                 const float* __restrict__ o2,
                 const float* __restrict__ s2,
                 const float* __restrict__ df,
                 float* __restrict__ out)
{
    float* b0x = sstage;
    float* b0y = b0x + HALF;
    float* b0z = b0y + HALF;
    float* b1x = sstage + 3 * HALF;
    float* b1y = b1x + HALF;
    float* b1z = b1y + HALF;
    __shared__ float wt0[3][NWARP], wt1[3][NWARP];
    __shared__ float red[NWARP];
    __shared__ int   is_last;

    const int b = blockIdx.x;
    const int t = threadIdx.x;
    const unsigned lane = t & 31u;
    const unsigned warp = t >> 5;

    const float* __restrict__ s3b = s3 + (size_t)b * (3 * NPTS);
    const float* __restrict__ s2b = s2 + (size_t)b * (3 * NPTS);
    const float* __restrict__ dfb = df + (size_t)b * (2 * NPTS);

    // ================= Phase A0: elements [0,2048) -> buf0 =================
    #pragma unroll
    for (int k = 0; k < LEPT; k++) {
        const int i = t + k * TPB;             // 0..2047, coalesced
        float r3  = s3b[i];
        float th3 = s3b[i + NPTS];
        float ph3 = s3b[i + 2 * NPTS];
        float r2  = s2b[i];
        float th2 = s2b[i + NPTS];
        float ph2 = s2b[i + 2 * NPTS];
        float dt  = dfb[i];
        float dp  = dfb[i + NPTS];

        float st, ct, sp, cp;
        __sincosf(th3 + dt, &st, &ct);
        __sincosf(ph3 + dp, &sp, &cp);
        float rst = r3 * st;
        float vx = rst * cp, vy = rst * sp, vz = r3 * ct;
        __sincosf(th2, &st, &ct);
        __sincosf(ph2, &sp, &cp);
        rst = r2 * st;
        b0x[i] = vx - rst * cp;
        b0y[i] = vy - rst * sp;
        b0z[i] = vz - r2 * ct;
    }
    __syncthreads();                            // bar 1

    // ====== Phase A1: elements [2048,4096) -> buf1 (loads issued BEFORE
    //        any pass-0 scan work, so DRAM stays busy during B0a) ======
    #pragma unroll
    for (int k = 0; k < LEPT; k++) {
        const int i = t + k * TPB;              // 0..2047
        const int g = i + HALF;
        float vx = 0.f, vy = 0.f, vz = 0.f;
        if (g < NPTS) {                          // only g==4095 fails
            float r3  = s3b[g];
            float th3 = s3b[g + NPTS];
            float ph3 = s3b[g + 2 * NPTS];
            float r2  = s2b[g];
            float th2 = s2b[g + NPTS];
            float ph2 = s2b[g + 2 * NPTS];
            float dt  = dfb[g];
            float dp  = dfb[g + NPTS];

            float st, ct, sp, cp;
            __sincosf(th3 + dt, &st, &ct);
            __sincosf(ph3 + dp, &sp, &cp);
            float rst = r3 * st;
            vx = rst * cp; vy = rst * sp; vz = r3 * ct;
            __sincosf(th2, &st, &ct);
            __sincosf(ph2, &sp, &cp);
            rst = r2 * st;
            vx -= rst * cp; vy -= rst * sp; vz -= r2 * ct;
        }
        b1x[i] = vx; b1y[i] = vy; b1z[i] = vz;
    }

    // origin deltas (tiny loads; L2-resident after wave 1)
    const float dx = o3[b * 3 + 0] - o2[b * 3 + 0];
    const float dy = o3[b * 3 + 1] - o2[b * 3 + 1];
    const float dz = o3[b * 3 + 2] - o2[b * 3 + 2];
    float offx = dx, offy = dy, offz = dz;      // running offset (incl. origin)

    float acc = 0.f;
    if (t == 0) acc = fabsf(dx) + fabsf(dy) + fabsf(dz);   // j=0 (origin)

    const int base = LEPT * t;                  // 16B-aligned float4 slot

    // ================= B0a: sum sweep + warp scan (buf0) =================
    float tx0, ty0, tz0;
    {
        float4 X = *reinterpret_cast<const float4*>(b0x + base);
        float4 Y = *reinterpret_cast<const float4*>(b0y + base);
        float4 Z = *reinterpret_cast<const float4*>(b0z + base);
        tx0 = (X.x + X.y) + (X.z + X.w);
        ty0 = (Y.x + Y.y) + (Y.z + Y.w);
        tz0 = (Z.x + Z.y) + (Z.z + Z.w);
    }
    float ix0 = tx0, iy0 = ty0, iz0 = tz0;
    #pragma unroll
    for (int o = 1; o < 32; o <<= 1) {
        float ax = __shfl_up_sync(0xFFFFFFFFu, ix0, o);
        float ay = __shfl_up_sync(0xFFFFFFFFu, iy0, o);
        float az = __shfl_up_sync(0xFFFFFFFFu, iz0, o);
        if (lane >= (unsigned)o) { ix0 += ax; iy0 += ay; iz0 += az; }
    }
    if (lane == 31) { wt0[0][warp] = ix0; wt0[1][warp] = iy0; wt0[2][warp] = iz0; }
    __syncthreads();                            // bar 2 (also fences buf1 stores)

    // ================= B0b: warp-total scan + abs sweep (buf0) ===========
    {
        float px = (lane < NWARP) ? wt0[0][lane] : 0.f;
        float py = (lane < NWARP) ? wt0[1][lane] : 0.f;
        float pz = (lane < NWARP) ? wt0[2][lane] : 0.f;
        #pragma unroll
        for (int o = 1; o < NWARP; o <<= 1) {
            float ax = __shfl_up_sync(0xFFFFFFFFu, px, o);
            float ay = __shfl_up_sync(0xFFFFFFFFu, py, o);
            float az = __shfl_up_sync(0xFFFFFFFFu, pz, o);
            if (lane >= (unsigned)o) { px += ax; py += ay; pz += az; }
        }
        const unsigned src = (warp == 0) ? 0u : (warp - 1u);
        float wpx = __shfl_sync(0xFFFFFFFFu, px, src);
        float wpy = __shfl_sync(0xFFFFFFFFu, py, src);
        float wpz = __shfl_sync(0xFFFFFFFFu, pz, src);
        float ox = offx + (ix0 - tx0) + ((warp == 0) ? 0.f : wpx);
        float oy = offy + (iy0 - ty0) + ((warp == 0) ? 0.f : wpy);
        float oz = offz + (iz0 - tz0) + ((warp == 0) ? 0.f : wpz);

        float4 X = *reinterpret_cast<const float4*>(b0x + base);
        float4 Y = *reinterpret_cast<const float4*>(b0y + base);
        float4 Z = *reinterpret_cast<const float4*>(b0z + base);
        float xs[LEPT] = {X.x, X.y, X.z, X.w};
        float ys[LEPT] = {Y.x, Y.y, Y.z, Y.w};
        float zs[LEPT] = {Z.x, Z.y, Z.z, Z.w};
        #pragma unroll
        for (int k = 0; k < LEPT; k++) {
            ox += xs[k]; oy += ys[k]; oz += zs[k];
            acc += fabsf(ox) + fabsf(oy) + fabsf(oz);   // all pass-0 idx valid
        }

        // advance running offset by pass-0 block total
        offx += __shfl_sync(0xFFFFFFFFu, px, NWARP - 1);
        offy += __shfl_sync(0xFFFFFFFFu, py, NWARP - 1);
        offz += __shfl_sync(0xFFFFFFFFu, pz, NWARP - 1);
    }

    // ================= B1a: sum sweep + warp scan (buf1) =================
    float tx1, ty1, tz1;
    {
        float4 X = *reinterpret_cast<const float4*>(b1x + base);
        float4 Y = *reinterpret_cast<const float4*>(b1y + base);
        float4 Z = *reinterpret_cast<const float4*>(b1z + base);
        tx1 = (X.x + X.y) + (X.z + X.w);
        ty1 = (Y.x + Y.y) + (Y.z + Y.w);
        tz1 = (Z.x + Z.y) + (Z.z + Z.w);
    }
    float ix1 = tx1, iy1 = ty1, iz1 = tz1;
    #pragma unroll
    for (int o = 1; o < 32; o <<= 1) {
        float ax = __shfl_up_sync(0xFFFFFFFFu, ix1, o);
        float ay = __shfl_up_sync(0xFFFFFFFFu, iy1, o);
        float az = __shfl_up_sync(0xFFFFFFFFu, iz1, o);
        if (lane >= (unsigned)o) { ix1 += ax; iy1 += ay; iz1 += az; }
    }
    if (lane == 31) { wt1[0][warp] = ix1; wt1[1][warp] = iy1; wt1[2][warp] = iz1; }
    __syncthreads();                            // bar 3

    // ================= B1b: warp-total scan + abs sweep (buf1) ===========
    {
        float px = (lane < NWARP) ? wt1[0][lane] : 0.f;
        float py = (lane < NWARP) ? wt1[1][lane] : 0.f;
        float pz = (lane < NWARP) ? wt1[2][lane] : 0.f;
        #pragma unroll
        for (int o = 1; o < NWARP; o <<= 1) {
            float ax = __shfl_up_sync(0xFFFFFFFFu, px, o);
            float ay = __shfl_up_sync(0xFFFFFFFFu, py, o);
            float az = __shfl_up_sync(0xFFFFFFFFu, pz, o);
            if (lane >= (unsigned)o) { px += ax; py += ay; pz += az; }
        }
        const unsigned src = (warp == 0) ? 0u : (warp - 1u);
        float wpx = __shfl_sync(0xFFFFFFFFu, px, src);
        float wpy = __shfl_sync(0xFFFFFFFFu, py, src);
        float wpz = __shfl_sync(0xFFFFFFFFu, pz, src);
        float ox = offx + (ix1 - tx1) + ((warp == 0) ? 0.f : wpx);
        float oy = offy + (iy1 - ty1) + ((warp == 0) ? 0.f : wpy);
        float oz = offz + (iz1 - tz1) + ((warp == 0) ? 0.f : wpz);

        float4 X = *reinterpret_cast<const float4*>(b1x + base);
        float4 Y = *reinterpret_cast<const float4*>(b1y + base);
        float4 Z = *reinterpret_cast<const float4*>(b1z + base);
        float xs[LEPT] = {X.x, X.y, X.z, X.w};
        float ys[LEPT] = {Y.x, Y.y, Y.z, Y.w};
        float zs[LEPT] = {Z.x, Z.y, Z.z, Z.w};
        #pragma unroll
        for (int k = 0; k < LEPT; k++) {
            ox += xs[k]; oy += ys[k]; oz += zs[k];
            if (HALF + base + k < NPTS)
                acc += fabsf(ox) + fabsf(oy) + fabsf(oz);
        }
    }

    // ================= block reduce =================
    #pragma unroll
    for (int o = 16; o > 0; o >>= 1)
        acc += __shfl_down_sync(0xFFFFFFFFu, acc, o);
    if (lane == 0) red[warp] = acc;
    __syncthreads();
    if (warp == 0) {
        float a = (lane < NWARP) ? red[lane] : 0.f;
        #pragma unroll
        for (int o = 16; o > 0; o >>= 1)
            a += __shfl_down_sync(0xFFFFFFFFu, a, o);
        if (lane == 0) g_partial[b] = a * (1.0f / (NPTS + 1));
    }

    // ================= fused deterministic final reduction =================
    if (t == 0) {
        __threadfence();
        int ticket = atomicAdd(&g_count, 1);
        is_last = (ticket == (int)gridDim.x - 1) ? 1 : 0;
    }
    __syncthreads();
    if (is_last) {
        float a = __ldcg(&g_partial[t])
                + __ldcg(&g_partial[t + TPB])
                + __ldcg(&g_partial[t + 2 * TPB])
                + __ldcg(&g_partial[t + 3 * TPB]);
        #pragma unroll
        for (int o = 16; o > 0; o >>= 1)
            a += __shfl_down_sync(0xFFFFFFFFu, a, o);
        if (lane == 0) red[warp] = a;
        __syncthreads();
        if (warp == 0) {
            float v = (lane < NWARP) ? red[lane] : 0.f;
            #pragma unroll
            for (int o = 16; o > 0; o >>= 1)
                v += __shfl_down_sync(0xFFFFFFFFu, v, o);
            if (lane == 0) {
                out[0] = v;
                atomicExch(&g_count, 0);   // reset for next graph replay
            }
        }
    }
}

extern "C" void kernel_launch(void* const* d_in, const int* in_sizes, int n_in,
                              void* d_out, int out_size)
{
    const float* o3 = (const float*)d_in[0];  // origin_3D        (B,3,1)
    const float* s3 = (const float*)d_in[1];  // spherical_3D     (B,3,N)
    const float* o2 = (const float*)d_in[2];  // origin_2D        (B,3,1)
    const float* s2 = (const float*)d_in[3];  // spherical_2D     (B,3,N)
    const float* df = (const float*)d_in[4];  // deformation_field(B,2,N)
    float* out = (float*)d_out;

    cudaFuncSetAttribute(mpd_fused_kernel,
                         cudaFuncAttributeMaxDynamicSharedMemorySize, SMEM_BYTES);
    mpd_fused_kernel<<<BATCH, TPB, SMEM_BYTES>>>(o3, s3, o2, s2, df, out);
}